// round 16
// baseline (speedup 1.0000x reference)
#include <cuda_runtime.h>

// Problem constants
#define BB 2
#define NN 200000
#define CC 16
#define DD 256
#define HH 256
#define WW 32
#define VV (DD * HH * WW)          // 2097152 = 2^21
#define LOGV 21

// Scratch: zero-initialized at module load. Invariant maintained by
// finalize_kernel: scratch is all-zero at entry of every kernel_launch.
__device__ float4 g_sums[(size_t)BB * VV * 4];   // [B,V,16] fp32, as 4x float4
__device__ float  g_cnt[(size_t)BB * VV];        // [B,V]

__device__ __forceinline__ int voxel_idx(float p, float lo, float range, float dim, int dmax) {
    // Mirror reference exactly: (p - lo) / (hi - lo) * D, truncate, clamp
    float t = __fmul_rn(__fdiv_rn(__fsub_rn(p, lo), range), dim);
    int i = (int)t;                // trunc toward zero, matches astype(int32)
    i = i < 0 ? 0 : i;
    i = i > dmax ? dmax : i;
    return i;
}

// One point's scatter: lane i of the quad handles channel group i.
// Single-use input loads use __ldcs (streaming; round-15 proven win).
__device__ __forceinline__ void scatter_one(int p, int i, int b,
                                            const float* __restrict__ pts,
                                            const float* __restrict__ fts) {
    int flat = 0;
    if (i == 0) {
        float x = __ldcs(pts + 3 * p + 0);
        float y = __ldcs(pts + 3 * p + 1);
        float z = __ldcs(pts + 3 * p + 2);
        int vx = voxel_idx(x, -48.0f, 96.0f, 256.0f, DD - 1);
        int vy = voxel_idx(y, -48.0f, 96.0f, 256.0f, HH - 1);
        int vz = voxel_idx(z,  -4.0f,  5.5f,  32.0f, WW - 1);
        flat = (vx * HH + vy) * WW + vz;
    }
    flat = __shfl_sync(0xffffffffu, flat, 0, 4);   // broadcast within quad

    size_t g = ((size_t)b << LOGV) + (size_t)flat;

    if (i == 0) atomicAdd(&g_cnt[g], 1.0f);

    // lane-consecutive 16B chunks: perfectly coalesced, streaming
    float4 v = __ldcs(reinterpret_cast<const float4*>(fts) + 4 * (size_t)p + i);
    float4* s = &g_sums[g * 4 + i];
    asm volatile("red.global.add.v4.f32 [%0], {%1,%2,%3,%4};"
                 :: "l"(s), "f"(v.x), "f"(v.y), "f"(v.z), "f"(v.w)
                 : "memory");
}

// ---- scatter: 4 lanes/point, 2 points per thread (batch0 q, batch1 q+NN) ----
__global__ void scatter_kernel(const float* __restrict__ pts,
                               const float* __restrict__ fts) {
    int t = blockIdx.x * blockDim.x + threadIdx.x;
    if (t >= 4 * NN) return;

    int q = t >> 2;                // local point index 0..NN-1
    int i = t & 3;                 // channel group 0..3

    scatter_one(q,      i, 0, pts, fts);   // batch 0
    scatter_one(q + NN, i, 1, pts, fts);   // batch 1
}

// Exact R1 per-voxel body. The fdiv sequences are load-bearing: they space
// out the memory ops (low MLP_p1 -> no cross-CTA L1tex queue pileup).
// ONLY delta vs round-15: output stores __stcs -> __stwt (write-through,
// full L2 bypass; the output is write-once, never read).
__device__ __forceinline__ void finalize_one(int g, float* __restrict__ o) {
    float c = g_cnt[g];
    float4 a0 = make_float4(0.f, 0.f, 0.f, 0.f);
    float4 a1 = a0, a2 = a0, a3 = a0;

    if (c > 0.0f) {
        float4* s = &g_sums[(size_t)g * 4];
        a0 = s[0]; a1 = s[1]; a2 = s[2]; a3 = s[3];
        a0.x = __fdiv_rn(a0.x, c); a0.y = __fdiv_rn(a0.y, c);
        a0.z = __fdiv_rn(a0.z, c); a0.w = __fdiv_rn(a0.w, c);
        a1.x = __fdiv_rn(a1.x, c); a1.y = __fdiv_rn(a1.y, c);
        a1.z = __fdiv_rn(a1.z, c); a1.w = __fdiv_rn(a1.w, c);
        a2.x = __fdiv_rn(a2.x, c); a2.y = __fdiv_rn(a2.y, c);
        a2.z = __fdiv_rn(a2.z, c); a2.w = __fdiv_rn(a2.w, c);
        a3.x = __fdiv_rn(a3.x, c); a3.y = __fdiv_rn(a3.y, c);
        a3.z = __fdiv_rn(a3.z, c); a3.w = __fdiv_rn(a3.w, c);
        float4 z4 = make_float4(0.f, 0.f, 0.f, 0.f);
        s[0] = z4; s[1] = z4; s[2] = z4; s[3] = z4;
        g_cnt[g] = 0.0f;
    }

    float vals[CC] = {a0.x, a0.y, a0.z, a0.w,
                      a1.x, a1.y, a1.z, a1.w,
                      a2.x, a2.y, a2.z, a2.w,
                      a3.x, a3.y, a3.z, a3.w};
#pragma unroll
    for (int ch = 0; ch < CC; ch++) {
        __stwt(o + (size_t)ch * VV, vals[ch]);   // coalesced, write-through (never re-read)
    }
}

// One thread handles voxel v of batch 0 AND voxel v of batch 1, sequentially
// (round-9 structure; best measured configuration).
__global__ void finalize_kernel(float* __restrict__ out) {
    int v = blockIdx.x * blockDim.x + threadIdx.x;   // 0 .. VV-1
    if (v >= VV) return;
    finalize_one(v,      out + v);                    // batch 0
    finalize_one(VV + v, out + (size_t)CC * VV + v);  // batch 1
}

extern "C" void kernel_launch(void* const* d_in, const int* in_sizes, int n_in,
                              void* d_out, int out_size) {
    const float* pts = (const float*)d_in[0];   // [B,N,3] f32
    const float* fts = (const float*)d_in[1];   // [B,N,16] f32
    float* out = (float*)d_out;                 // [B,16,D,H,W] f32

    const int nthr = 4 * NN;                    // 2 points per thread
    scatter_kernel<<<(nthr + 255) / 256, 256>>>(pts, fts);

    finalize_kernel<<<VV / 256, 256>>>(out);
}

// round 17
// speedup vs baseline: 1.2670x; 1.2670x over previous
#include <cuda_runtime.h>

// Problem constants
#define BB 2
#define NN 200000
#define CC 16
#define DD 256
#define HH 256
#define WW 32
#define VV (DD * HH * WW)          // 2097152 = 2^21
#define LOGV 21

// Scratch: zero-initialized at module load. Invariant maintained by
// finalize_kernel: scratch is all-zero at entry of every kernel_launch.
__device__ float4 g_sums[(size_t)BB * VV * 4];   // [B,V,16] fp32, as 4x float4
__device__ float  g_cnt[(size_t)BB * VV];        // [B,V]

__device__ __forceinline__ int voxel_idx(float p, float lo, float range, float dim, int dmax) {
    // Mirror reference exactly: (p - lo) / (hi - lo) * D, truncate, clamp
    float t = __fmul_rn(__fdiv_rn(__fsub_rn(p, lo), range), dim);
    int i = (int)t;                // trunc toward zero, matches astype(int32)
    i = i < 0 ? 0 : i;
    i = i > dmax ? dmax : i;
    return i;
}

// One point's scatter: lane i of the quad handles channel group i.
// Single-use input loads use __ldcs (streaming; round-15 proven win).
__device__ __forceinline__ void scatter_one(int p, int i, int b,
                                            const float* __restrict__ pts,
                                            const float* __restrict__ fts) {
    int flat = 0;
    if (i == 0) {
        float x = __ldcs(pts + 3 * p + 0);
        float y = __ldcs(pts + 3 * p + 1);
        float z = __ldcs(pts + 3 * p + 2);
        int vx = voxel_idx(x, -48.0f, 96.0f, 256.0f, DD - 1);
        int vy = voxel_idx(y, -48.0f, 96.0f, 256.0f, HH - 1);
        int vz = voxel_idx(z,  -4.0f,  5.5f,  32.0f, WW - 1);
        flat = (vx * HH + vy) * WW + vz;
    }
    flat = __shfl_sync(0xffffffffu, flat, 0, 4);   // broadcast within quad

    size_t g = ((size_t)b << LOGV) + (size_t)flat;

    if (i == 0) atomicAdd(&g_cnt[g], 1.0f);

    // lane-consecutive 16B chunks: perfectly coalesced, streaming
    float4 v = __ldcs(reinterpret_cast<const float4*>(fts) + 4 * (size_t)p + i);
    float4* s = &g_sums[g * 4 + i];
    asm volatile("red.global.add.v4.f32 [%0], {%1,%2,%3,%4};"
                 :: "l"(s), "f"(v.x), "f"(v.y), "f"(v.z), "f"(v.w)
                 : "memory");
}

// ---- scatter: 4 lanes/point, 2 points per thread (batch0 q, batch1 q+NN) ----
__global__ void scatter_kernel(const float* __restrict__ pts,
                               const float* __restrict__ fts) {
    int t = blockIdx.x * blockDim.x + threadIdx.x;
    if (t >= 4 * NN) return;

    int q = t >> 2;                // local point index 0..NN-1
    int i = t & 3;                 // channel group 0..3

    scatter_one(q,      i, 0, pts, fts);   // batch 0
    scatter_one(q + NN, i, 1, pts, fts);   // batch 1
}

// Exact R1 per-voxel body. The fdiv sequences are load-bearing: they space
// out the memory ops (low MLP_p1 -> no cross-CTA L1tex queue pileup).
// Output stores are __stcs (streaming; round-13 proven win).
// FORBIDDEN by measurement: __frcp_rn (4x collapse), __stwt (+18us),
// smem-staged transpose (+10us), per-thread multi-voxel strided layouts.
__device__ __forceinline__ void finalize_one(int g, float* __restrict__ o) {
    float c = g_cnt[g];
    float4 a0 = make_float4(0.f, 0.f, 0.f, 0.f);
    float4 a1 = a0, a2 = a0, a3 = a0;

    if (c > 0.0f) {
        float4* s = &g_sums[(size_t)g * 4];
        a0 = s[0]; a1 = s[1]; a2 = s[2]; a3 = s[3];
        a0.x = __fdiv_rn(a0.x, c); a0.y = __fdiv_rn(a0.y, c);
        a0.z = __fdiv_rn(a0.z, c); a0.w = __fdiv_rn(a0.w, c);
        a1.x = __fdiv_rn(a1.x, c); a1.y = __fdiv_rn(a1.y, c);
        a1.z = __fdiv_rn(a1.z, c); a1.w = __fdiv_rn(a1.w, c);
        a2.x = __fdiv_rn(a2.x, c); a2.y = __fdiv_rn(a2.y, c);
        a2.z = __fdiv_rn(a2.z, c); a2.w = __fdiv_rn(a2.w, c);
        a3.x = __fdiv_rn(a3.x, c); a3.y = __fdiv_rn(a3.y, c);
        a3.z = __fdiv_rn(a3.z, c); a3.w = __fdiv_rn(a3.w, c);
        float4 z4 = make_float4(0.f, 0.f, 0.f, 0.f);
        s[0] = z4; s[1] = z4; s[2] = z4; s[3] = z4;
        g_cnt[g] = 0.0f;
    }

    float vals[CC] = {a0.x, a0.y, a0.z, a0.w,
                      a1.x, a1.y, a1.z, a1.w,
                      a2.x, a2.y, a2.z, a2.w,
                      a3.x, a3.y, a3.z, a3.w};
#pragma unroll
    for (int ch = 0; ch < CC; ch++) {
        __stcs(o + (size_t)ch * VV, vals[ch]);   // coalesced, streaming (never re-read)
    }
}

// One thread handles voxel v of batch 0 AND voxel v of batch 1, sequentially
// (round-9 structure; best measured configuration).
__global__ void finalize_kernel(float* __restrict__ out) {
    int v = blockIdx.x * blockDim.x + threadIdx.x;   // 0 .. VV-1
    if (v >= VV) return;
    finalize_one(v,      out + v);                    // batch 0
    finalize_one(VV + v, out + (size_t)CC * VV + v);  // batch 1
}

extern "C" void kernel_launch(void* const* d_in, const int* in_sizes, int n_in,
                              void* d_out, int out_size) {
    const float* pts = (const float*)d_in[0];   // [B,N,3] f32
    const float* fts = (const float*)d_in[1];   // [B,N,16] f32
    float* out = (float*)d_out;                 // [B,16,D,H,W] f32

    const int nthr = 4 * NN;                    // 2 points per thread
    scatter_kernel<<<(nthr + 255) / 256, 256>>>(pts, fts);

    finalize_kernel<<<VV / 256, 256>>>(out);
}